// round 7
// baseline (speedup 1.0000x reference)
#include <cuda_runtime.h>
#include <cstdint>
#include <math.h>

using ll = long long;

constexpr int B_ = 4, S_ = 2048, E_ = 2048, H_ = 16, D_ = 128;
constexpr int M_TOK = B_ * S_;        // 8192
constexpr int QKV_N = 3 * H_ * D_;    // 6144
constexpr float RMS_EPS = 0.01f;
constexpr float SM_SCALE = 0.08838834764831845f;  // 1/sqrt(128)
constexpr float LOG2E = 1.4426950408889634f;

// ---------------- scratch (static device arrays; no cudaMalloc) ------------
__device__ float g_xr[(size_t)M_TOK * E_];             // 64 MB
__device__ float g_qkv[(size_t)M_TOK * QKV_N];         // 201 MB
__device__ float g_wqkvT[(size_t)QKV_N * E_];          // 50 MB
__device__ float g_wprojT[(size_t)E_ * E_];            // 16 MB
__device__ float g_vT[(size_t)B_ * H_ * D_ * S_];      // 67 MB
__device__ float g_attn[(size_t)M_TOK * H_ * D_];      // 67 MB
__device__ float g_cos[S_ * 64];
__device__ float g_sin[S_ * 64];

// ---------------- helpers --------------------------------------------------
__device__ __forceinline__ float rnd_tf32(float x) {
    uint32_t u;
    asm("cvt.rna.tf32.f32 %0, %1;" : "=r"(u) : "f"(x));
    return __uint_as_float(u);
}
__device__ __forceinline__ float ex2f(float x) {
    float y;
    asm("ex2.approx.ftz.f32 %0, %1;" : "=f"(y) : "f"(x));
    return y;
}
__device__ __forceinline__ uint32_t smem_u32(const void* p) {
    uint32_t a;
    asm("{ .reg .u64 t; cvta.to.shared.u64 t, %1; cvt.u32.u64 %0, t; }"
        : "=r"(a) : "l"(p));
    return a;
}
#define SWZ128(off) ((off) ^ (((off) >> 3) & 0x70))

// ---------------------------------------------------------------------------
__global__ void rope_table_kernel() {
    int idx = blockIdx.x * blockDim.x + threadIdx.x;
    if (idx >= S_ * 64) return;
    int s = idx >> 6, d = idx & 63;
    double f = pow(10000.0, -(double)d / 64.0);
    double ang = (double)s * f;
    g_cos[idx] = (float)cos(ang);
    g_sin[idx] = (float)sin(ang);
}

__global__ void round_copy(const float* __restrict__ in, float* __restrict__ out,
                           int n4) {
    int i = blockIdx.x * blockDim.x + threadIdx.x;
    if (i >= n4) return;
    float4 v = ((const float4*)in)[i];
    v.x = rnd_tf32(v.x); v.y = rnd_tf32(v.y);
    v.z = rnd_tf32(v.z); v.w = rnd_tf32(v.w);
    ((float4*)out)[i] = v;
}

__global__ void transpose_round(const float* __restrict__ in, ll ldi, ll sIb, ll sIh,
                                float* __restrict__ out, ll ldo, ll sOb, ll sOh) {
    __shared__ float t[32][33];
    const int z = blockIdx.z, zb = z >> 4, zh = z & 15;
    in += zb * sIb + zh * sIh;
    out += zb * sOb + zh * sOh;
    int k0 = blockIdx.y * 32, n0 = blockIdx.x * 32;
    int tx = threadIdx.x, ty = threadIdx.y;
#pragma unroll
    for (int i = 0; i < 4; i++)
        t[ty + i * 8][tx] = in[(ll)(k0 + ty + i * 8) * ldi + n0 + tx];
    __syncthreads();
#pragma unroll
    for (int i = 0; i < 4; i++)
        out[(ll)(n0 + ty + i * 8) * ldo + k0 + tx] = rnd_tf32(t[tx][ty + i * 8]);
}

__global__ void norm_rope_kernel(const float* __restrict__ qw,
                                 const float* __restrict__ kw) {
    int gw = blockIdx.x * 8 + (threadIdx.x >> 5);
    int lane = threadIdx.x & 31;
    int m = gw >> 5;
    int rem = gw & 31;
    int qk = rem >> 4;
    int h = rem & 15;
    float* p = g_qkv + (size_t)m * QKV_N + qk * (H_ * D_) + h * D_;

    float x0 = p[lane], x1 = p[lane + 32], x2 = p[lane + 64], x3 = p[lane + 96];
    float ss = x0 * x0 + x1 * x1 + x2 * x2 + x3 * x3;
#pragma unroll
    for (int o = 16; o; o >>= 1) ss += __shfl_xor_sync(0xffffffffu, ss, o);
    float inv = rsqrtf(ss * (1.0f / 128.0f) + RMS_EPS);

    const float* w = qk ? kw : qw;
    float n0 = x0 * inv * w[lane];
    float n1 = x1 * inv * w[lane + 32];
    float n2 = x2 * inv * w[lane + 64];
    float n3 = x3 * inv * w[lane + 96];

    int s = m & (S_ - 1);
    float c0 = g_cos[s * 64 + lane],      sn0 = g_sin[s * 64 + lane];
    float c1 = g_cos[s * 64 + lane + 32], sn1 = g_sin[s * 64 + lane + 32];

    float o0 = n0 * c0 - n2 * sn0;
    float o1 = n1 * c1 - n3 * sn1;
    float o2 = n2 * c0 + n0 * sn0;
    float o3 = n3 * c1 + n1 * sn1;
    if (!qk) { o0 *= SM_SCALE; o1 *= SM_SCALE; o2 *= SM_SCALE; o3 *= SM_SCALE; }
    p[lane]      = rnd_tf32(o0);
    p[lane + 32] = rnd_tf32(o1);
    p[lane + 64] = rnd_tf32(o2);
    p[lane + 96] = rnd_tf32(o3);
}

// ---------------------------------------------------------------------------
// tf32 mma.sync GEMM: C[M,N] = A[M,K] * B[N,K]^T (both K-major in gmem).
// 128x128 CTA tile, BK=32 (SW128), 4-stage cp.async pipeline, 256 threads,
// 8 warps of 64x32. B fragments now via ldmatrix.x4 (j-pairs).
// ---------------------------------------------------------------------------
constexpr int N_STAGE = 4;
constexpr int STAGE_BYTES = 32768;
constexpr int SMEM_GEMM = N_STAGE * STAGE_BYTES;

__global__ __launch_bounds__(256) void gemm_mma(
    const float* __restrict__ A, ll lda,
    const float* __restrict__ B, ll ldb,
    float* __restrict__ C, ll ldc, int K) {
    const int bx = blockIdx.x, by = blockIdx.y;
    const int m0 = by * 128, n0 = bx * 128;
    const int nT = K >> 5;

    extern __shared__ char smem[];
    const uint32_t base = smem_u32(smem);

    const int tid = threadIdx.x;
    const int warp = tid >> 5, lane = tid & 31;
    const int wm = warp >> 2, wn = warp & 3;

    const int c16 = (tid & 7) * 16;
    const int r0 = tid >> 3;

    auto load_stage = [&](int kt) {
        const uint32_t sa = base + (kt & (N_STAGE - 1)) * STAGE_BYTES;
        const uint32_t sb = sa + 16384;
        const float* Ap = A + kt * 32;
        const float* Bp = B + kt * 32;
#pragma unroll
        for (int p = 0; p < 4; p++) {
            int r = r0 + p * 32;
            uint32_t off = SWZ128((uint32_t)(r * 128 + c16));
            const char* ga = (const char*)(Ap + (ll)(m0 + r) * lda) + c16;
            asm volatile("cp.async.cg.shared.global [%0], [%1], 16;"
                         :: "r"(sa + off), "l"(ga));
            const char* gb = (const char*)(Bp + (ll)(n0 + r) * ldb) + c16;
            asm volatile("cp.async.cg.shared.global [%0], [%1], 16;"
                         :: "r"(sb + off), "l"(gb));
        }
        asm volatile("cp.async.commit_group;" ::: "memory");
    };

    const int lq = lane & 7;
    const int aRowIn16 = lq + (((lane >> 3) & 1) << 3);
    const int aSel = lane >> 4;
    const int bSel = (lane >> 3) & 1;
    const int bRow4 = ((lane >> 4) << 3) + lq;  // x4 B: second half -> +8 rows

    float acc[4][4][4];
#pragma unroll
    for (int i = 0; i < 4; i++)
#pragma unroll
        for (int j = 0; j < 4; j++)
#pragma unroll
            for (int r = 0; r < 4; r++) acc[i][j][r] = 0.0f;

    load_stage(0);
    load_stage(1);
    load_stage(2);

    for (int kt = 0; kt < nT; kt++) {
        asm volatile("cp.async.wait_group 2;" ::: "memory");
        __syncthreads();
        if (kt + 3 < nT) load_stage(kt + 3);
        else asm volatile("cp.async.commit_group;" ::: "memory");

        const uint32_t sa = base + (kt & (N_STAGE - 1)) * STAGE_BYTES;
        const uint32_t sb = sa + 16384;
        const uint32_t aBase = sa + (uint32_t)(wm * 64 + aRowIn16) * 128;
        const uint32_t bBase4 = sb + (uint32_t)(wn * 32 + bRow4) * 128;

#pragma unroll
        for (int g = 0; g < 4; g++) {
            uint32_t af[4][4];
#pragma unroll
            for (int i = 0; i < 4; i++) {
                uint32_t addr = aBase + i * 16 * 128 +
                                16u * (uint32_t)(((g << 1) | aSel) ^ lq);
                asm volatile(
                    "ldmatrix.sync.aligned.m8n8.x4.shared.b16 {%0,%1,%2,%3}, [%4];"
                    : "=r"(af[i][0]), "=r"(af[i][1]), "=r"(af[i][2]), "=r"(af[i][3])
                    : "r"(addr));
            }
            uint32_t bf[4][2];
#pragma unroll
            for (int jp = 0; jp < 2; jp++) {
                uint32_t addr = bBase4 + jp * 16 * 128 +
                                16u * (uint32_t)(((g << 1) | bSel) ^ lq);
                asm volatile(
                    "ldmatrix.sync.aligned.m8n8.x4.shared.b16 {%0,%1,%2,%3}, [%4];"
                    : "=r"(bf[2 * jp][0]), "=r"(bf[2 * jp][1]),
                      "=r"(bf[2 * jp + 1][0]), "=r"(bf[2 * jp + 1][1])
                    : "r"(addr));
            }
#pragma unroll
            for (int i = 0; i < 4; i++)
#pragma unroll
                for (int j = 0; j < 4; j++) {
                    asm volatile(
                        "mma.sync.aligned.m16n8k8.row.col.f32.tf32.tf32.f32 "
                        "{%0,%1,%2,%3}, {%4,%5,%6,%7}, {%8,%9}, {%0,%1,%2,%3};"
                        : "+f"(acc[i][j][0]), "+f"(acc[i][j][1]),
                          "+f"(acc[i][j][2]), "+f"(acc[i][j][3])
                        : "r"(af[i][0]), "r"(af[i][1]), "r"(af[i][2]), "r"(af[i][3]),
                          "r"(bf[j][0]), "r"(bf[j][1]));
                }
        }
    }

    float* Cw = C + (ll)(m0 + wm * 64) * ldc + n0 + wn * 32;
    const int erow = lane >> 2, ecol = (lane & 3) * 2;
#pragma unroll
    for (int i = 0; i < 4; i++)
#pragma unroll
        for (int j = 0; j < 4; j++) {
            float2 v0, v1;
            v0.x = acc[i][j][0]; v0.y = acc[i][j][1];
            v1.x = acc[i][j][2]; v1.y = acc[i][j][3];
            float* cp = Cw + (ll)(i * 16 + erow) * ldc + j * 8 + ecol;
            *(float2*)cp = v0;
            *(float2*)(cp + 8 * ldc) = v1;
        }
}

// ---------------------------------------------------------------------------
// Fused flash attention (causal): per CTA one (q-tile, b, h).
// 8 warps x 16 q-rows. Q resident in smem; K / vT streamed as 16KB chunks
// through a 4-stage cp.async ring. B fragments via ldmatrix.x4 (j2-pairs).
// ---------------------------------------------------------------------------
constexpr int FA_SMEM = 65536 + 65536;

__global__ __launch_bounds__(256) void fa_kernel(
    const float* __restrict__ qkv_, const float* __restrict__ vT_,
    float* __restrict__ attn_) {
    const int qi = 15 - (int)blockIdx.x;       // heavy tiles first
    const int bh = blockIdx.y, b = bh >> 4, h = bh & 15;
    const float* Qb = qkv_ + (ll)(b * S_ + qi * 128) * QKV_N + h * 128;
    const float* Kb = qkv_ + (ll)b * S_ * QKV_N + H_ * D_ + h * 128;
    const float* Vb = vT_ + (ll)bh * D_ * S_;
    float* Ob = attn_ + (ll)(b * S_ + qi * 128) * (H_ * D_) + h * 128;

    extern __shared__ char smem[];
    const uint32_t qs = smem_u32(smem);
    const uint32_t ring = qs + 65536;

    const int tid = threadIdx.x, warp = tid >> 5, lane = tid & 31;
    const int c16 = (tid & 7) * 16, r0 = tid >> 3;

#pragma unroll
    for (int c = 0; c < 4; c++) {
#pragma unroll
        for (int p = 0; p < 4; p++) {
            int r = r0 + p * 32;
            uint32_t off = SWZ128((uint32_t)(r * 128 + c16));
            const char* g = (const char*)(Qb + (ll)r * QKV_N + c * 32) + c16;
            asm volatile("cp.async.cg.shared.global [%0], [%1], 16;"
                         :: "r"(qs + c * 16384 + off), "l"(g));
        }
    }
    asm volatile("cp.async.commit_group;" ::: "memory");

    const int total = (qi + 1) * 8;
    auto issue = [&](int ci) {
        if (ci < total) {
            const int kt = ci >> 3, rr = ci & 7;
            const float* gp;
            ll stride;
            if (rr < 4) { gp = Kb + (ll)kt * 128 * QKV_N + rr * 32; stride = QKV_N; }
            else        { gp = Vb + kt * 128 + (rr - 4) * 32;       stride = S_; }
            const uint32_t sa = ring + (ci & 3) * 16384;
#pragma unroll
            for (int p = 0; p < 4; p++) {
                int r = r0 + p * 32;
                uint32_t off = SWZ128((uint32_t)(r * 128 + c16));
                const char* g = (const char*)(gp + (ll)r * stride) + c16;
                asm volatile("cp.async.cg.shared.global [%0], [%1], 16;"
                             :: "r"(sa + off), "l"(g));
            }
        }
        asm volatile("cp.async.commit_group;" ::: "memory");
    };
    issue(0); issue(1); issue(2);

    const int lq = lane & 7;
    const int aRowIn16 = lq + (((lane >> 3) & 1) << 3);
    const int aSel = lane >> 4;
    const int bSel = (lane >> 3) & 1;
    const int bRow4 = ((lane >> 4) << 3) + lq;
    const int q4 = lane & 3;

    float m0 = -1e30f, m1 = -1e30f, l0 = 0.0f, l1 = 0.0f;
    float accO[16][4];
#pragma unroll
    for (int j = 0; j < 16; j++)
#pragma unroll
        for (int r = 0; r < 4; r++) accO[j][r] = 0.0f;

    int ci = 0;
    for (int kt = 0; kt <= qi; kt++) {
        float accS[16][4];
#pragma unroll
        for (int j = 0; j < 16; j++)
#pragma unroll
            for (int r = 0; r < 4; r++) accS[j][r] = 0.0f;

        // ---- S = Q * K^T over 4 d-chunks --------------------------------
        for (int c = 0; c < 4; c++) {
            asm volatile("cp.async.wait_group 2;" ::: "memory");
            __syncthreads();
            issue(ci + 3);
            const uint32_t sk = ring + (ci & 3) * 16384;
            const uint32_t aB = qs + c * 16384 + (uint32_t)(warp * 16 + aRowIn16) * 128;
            const uint32_t bB4 = sk + (uint32_t)bRow4 * 128;
#pragma unroll
            for (int g = 0; g < 4; g++) {
                uint32_t af[4];
                uint32_t aaddr = aB + 16u * (uint32_t)(((g << 1) | aSel) ^ lq);
                asm volatile(
                    "ldmatrix.sync.aligned.m8n8.x4.shared.b16 {%0,%1,%2,%3}, [%4];"
                    : "=r"(af[0]), "=r"(af[1]), "=r"(af[2]), "=r"(af[3])
                    : "r"(aaddr));
#pragma unroll
                for (int jp = 0; jp < 8; jp++) {
                    uint32_t bf0, bf1, bf2, bf3;
                    uint32_t baddr = bB4 + (uint32_t)(jp * 16 * 128) +
                                     16u * (uint32_t)(((g << 1) | bSel) ^ lq);
                    asm volatile(
                        "ldmatrix.sync.aligned.m8n8.x4.shared.b16 {%0,%1,%2,%3}, [%4];"
                        : "=r"(bf0), "=r"(bf1), "=r"(bf2), "=r"(bf3) : "r"(baddr));
                    asm volatile(
                        "mma.sync.aligned.m16n8k8.row.col.f32.tf32.tf32.f32 "
                        "{%0,%1,%2,%3}, {%4,%5,%6,%7}, {%8,%9}, {%0,%1,%2,%3};"
                        : "+f"(accS[2 * jp][0]), "+f"(accS[2 * jp][1]),
                          "+f"(accS[2 * jp][2]), "+f"(accS[2 * jp][3])
                        : "r"(af[0]), "r"(af[1]), "r"(af[2]), "r"(af[3]),
                          "r"(bf0), "r"(bf1));
                    asm volatile(
                        "mma.sync.aligned.m16n8k8.row.col.f32.tf32.tf32.f32 "
                        "{%0,%1,%2,%3}, {%4,%5,%6,%7}, {%8,%9}, {%0,%1,%2,%3};"
                        : "+f"(accS[2 * jp + 1][0]), "+f"(accS[2 * jp + 1][1]),
                          "+f"(accS[2 * jp + 1][2]), "+f"(accS[2 * jp + 1][3])
                        : "r"(af[0]), "r"(af[1]), "r"(af[2]), "r"(af[3]),
                          "r"(bf2), "r"(bf3));
                }
            }
            ci++;
        }

        // ---- causal mask on diagonal tile -------------------------------
        const int rW = warp * 16 + (lane >> 2);
        if (kt == qi) {
#pragma unroll
            for (int j2 = 0; j2 < 16; j2++) {
                int col = j2 * 8 + (q4 << 1);
                if (col     > rW)     accS[j2][0] = -1e30f;
                if (col + 1 > rW)     accS[j2][1] = -1e30f;
                if (col     > rW + 8) accS[j2][2] = -1e30f;
                if (col + 1 > rW + 8) accS[j2][3] = -1e30f;
            }
        }

        // ---- online softmax update --------------------------------------
        float mx0 = -1e30f, mx1 = -1e30f;
#pragma unroll
        for (int j2 = 0; j2 < 16; j2++) {
            mx0 = fmaxf(mx0, fmaxf(accS[j2][0], accS[j2][1]));
            mx1 = fmaxf(mx1, fmaxf(accS[j2][2], accS[j2][3]));
        }
        mx0 = fmaxf(mx0, __shfl_xor_sync(0xffffffffu, mx0, 1));
        mx0 = fmaxf(mx0, __shfl_xor_sync(0xffffffffu, mx0, 2));
        mx1 = fmaxf(mx1, __shfl_xor_sync(0xffffffffu, mx1, 1));
        mx1 = fmaxf(mx1, __shfl_xor_sync(0xffffffffu, mx1, 2));
        const float mn0 = fmaxf(m0, mx0), mn1 = fmaxf(m1, mx1);
        const float sc0 = ex2f((m0 - mn0) * LOG2E);
        const float sc1 = ex2f((m1 - mn1) * LOG2E);
        float rs0 = 0.0f, rs1 = 0.0f;
#pragma unroll
        for (int j2 = 0; j2 < 16; j2++) {
            float p0 = ex2f((accS[j2][0] - mn0) * LOG2E);
            float p1 = ex2f((accS[j2][1] - mn0) * LOG2E);
            float p2 = ex2f((accS[j2][2] - mn1) * LOG2E);
            float p3 = ex2f((accS[j2][3] - mn1) * LOG2E);
            rs0 += p0 + p1;
            rs1 += p2 + p3;
            accS[j2][0] = rnd_tf32(p0);
            accS[j2][1] = rnd_tf32(p1);
            accS[j2][2] = rnd_tf32(p2);
            accS[j2][3] = rnd_tf32(p3);
        }
        rs0 += __shfl_xor_sync(0xffffffffu, rs0, 1);
        rs0 += __shfl_xor_sync(0xffffffffu, rs0, 2);
        rs1 += __shfl_xor_sync(0xffffffffu, rs1, 1);
        rs1 += __shfl_xor_sync(0xffffffffu, rs1, 2);
        l0 = l0 * sc0 + rs0;
        l1 = l1 * sc1 + rs1;
#pragma unroll
        for (int j2 = 0; j2 < 16; j2++) {
            accO[j2][0] *= sc0; accO[j2][1] *= sc0;
            accO[j2][2] *= sc1; accO[j2][3] *= sc1;
        }
        m0 = mn0; m1 = mn1;

        // ---- accO += P * V over 4 s-chunks ------------------------------
        const int sbase = lane & ~3;
        const int s1 = sbase + (q4 >> 1), s2 = s1 + 2;
        const bool odd = (q4 & 1);
        for (int cc = 0; cc < 4; cc++) {
            asm volatile("cp.async.wait_group 2;" ::: "memory");
            __syncthreads();
            issue(ci + 3);
            const uint32_t sv = ring + (ci & 3) * 16384;
            const uint32_t bB4 = sv + (uint32_t)bRow4 * 128;
#pragma unroll
            for (int g = 0; g < 4; g++) {
                const int jt = cc * 4 + g;
                float v00 = __shfl_sync(0xffffffffu, accS[jt][0], s1);
                float v01 = __shfl_sync(0xffffffffu, accS[jt][1], s1);
                float v02 = __shfl_sync(0xffffffffu, accS[jt][0], s2);
                float v03 = __shfl_sync(0xffffffffu, accS[jt][1], s2);
                float v10 = __shfl_sync(0xffffffffu, accS[jt][2], s1);
                float v11 = __shfl_sync(0xffffffffu, accS[jt][3], s1);
                float v12 = __shfl_sync(0xffffffffu, accS[jt][2], s2);
                float v13 = __shfl_sync(0xffffffffu, accS[jt][3], s2);
                uint32_t a0 = __float_as_uint(odd ? v01 : v00);
                uint32_t a2 = __float_as_uint(odd ? v03 : v02);
                uint32_t a1 = __float_as_uint(odd ? v11 : v10);
                uint32_t a3 = __float_as_uint(odd ? v13 : v12);
#pragma unroll
                for (int jp = 0; jp < 8; jp++) {
                    uint32_t bf0, bf1, bf2, bf3;
                    uint32_t baddr = bB4 + (uint32_t)(jp * 16 * 128) +
                                     16u * (uint32_t)(((g << 1) | bSel) ^ lq);
                    asm volatile(
                        "ldmatrix.sync.aligned.m8n8.x4.shared.b16 {%0,%1,%2,%3}, [%4];"
                        : "=r"(bf0), "=r"(bf1), "=r"(bf2), "=r"(bf3) : "r"(baddr));
                    asm volatile(
                        "mma.sync.aligned.m16n8k8.row.col.f32.tf32.tf32.f32 "
                        "{%0,%1,%2,%3}, {%4,%5,%6,%7}, {%8,%9}, {%0,%1,%2,%3};"
                        : "+f"(accO[2 * jp][0]), "+f"(accO[2 * jp][1]),
                          "+f"(accO[2 * jp][2]), "+f"(accO[2 * jp][3])
                        : "r"(a0), "r"(a1), "r"(a2), "r"(a3),
                          "r"(bf0), "r"(bf1));
                    asm volatile(
                        "mma.sync.aligned.m16n8k8.row.col.f32.tf32.tf32.f32 "
                        "{%0,%1,%2,%3}, {%4,%5,%6,%7}, {%8,%9}, {%0,%1,%2,%3};"
                        : "+f"(accO[2 * jp + 1][0]), "+f"(accO[2 * jp + 1][1]),
                          "+f"(accO[2 * jp + 1][2]), "+f"(accO[2 * jp + 1][3])
                        : "r"(a0), "r"(a1), "r"(a2), "r"(a3),
                          "r"(bf2), "r"(bf3));
                }
            }
            ci++;
        }
    }

    // ---- normalize + store -----------------------------------------------
    const float inv0 = 1.0f / l0, inv1 = 1.0f / l1;
    const int rW = warp * 16 + (lane >> 2);
    float* o0 = Ob + (ll)rW * (H_ * D_) + (q4 << 1);
    float* o1 = o0 + 8 * (H_ * D_);
#pragma unroll
    for (int j2 = 0; j2 < 16; j2++) {
        float2 v0, v1;
        v0.x = rnd_tf32(accO[j2][0] * inv0);
        v0.y = rnd_tf32(accO[j2][1] * inv0);
        v1.x = rnd_tf32(accO[j2][2] * inv1);
        v1.y = rnd_tf32(accO[j2][3] * inv1);
        *(float2*)(o0 + j2 * 8) = v0;
        *(float2*)(o1 + j2 * 8) = v1;
    }
}

// ---------------------------------------------------------------------------
extern "C" void kernel_launch(void* const* d_in, const int* in_sizes, int n_in,
                              void* d_out, int out_size) {
    const float* x  = (const float*)d_in[0];
    const float* wq = (const float*)d_in[1];
    const float* wp = (const float*)d_in[2];
    const float* qw = (const float*)d_in[3];
    const float* kw = (const float*)d_in[4];
    float* y = (float*)d_out;

    float *xr, *qkv, *wqkvT, *wprojT, *vT, *attn;
    cudaGetSymbolAddress((void**)&xr, g_xr);
    cudaGetSymbolAddress((void**)&qkv, g_qkv);
    cudaGetSymbolAddress((void**)&wqkvT, g_wqkvT);
    cudaGetSymbolAddress((void**)&wprojT, g_wprojT);
    cudaGetSymbolAddress((void**)&vT, g_vT);
    cudaGetSymbolAddress((void**)&attn, g_attn);

    cudaFuncSetAttribute(gemm_mma,
                         cudaFuncAttributeMaxDynamicSharedMemorySize, SMEM_GEMM);
    cudaFuncSetAttribute(fa_kernel,
                         cudaFuncAttributeMaxDynamicSharedMemorySize, FA_SMEM);

    // launch index:                                     (ncu captures idx 3)
    // 0 rope, 1 round, 2 wqkvT, 3 QKV GEMM, 4 norm_rope, 5 wprojT, 6 vT,
    // 7 fa, 8 proj GEMM
    rope_table_kernel<<<(S_ * 64 + 255) / 256, 256>>>();
    round_copy<<<(M_TOK * E_ / 4 + 255) / 256, 256>>>(x, xr, M_TOK * E_ / 4);
    transpose_round<<<dim3(QKV_N / 32, E_ / 32, 1), dim3(32, 8)>>>(
        wq, QKV_N, 0, 0, wqkvT, E_, 0, 0);

    gemm_mma<<<dim3(QKV_N / 128, M_TOK / 128), 256, SMEM_GEMM>>>(
        xr, E_, wqkvT, E_, qkv, QKV_N, E_);

    norm_rope_kernel<<<(2 * M_TOK * H_) / 8, 256>>>(qw, kw);

    transpose_round<<<dim3(E_ / 32, E_ / 32, 1), dim3(32, 8)>>>(
        wp, E_, 0, 0, wprojT, E_, 0, 0);

    transpose_round<<<dim3(D_ / 32, S_ / 32, B_ * H_), dim3(32, 8)>>>(
        qkv + 2 * H_ * D_, QKV_N, (ll)S_ * QKV_N, 128,
        vT, S_, (ll)H_ * D_ * S_, (ll)D_ * S_);

    fa_kernel<<<dim3(16, 64), 256, FA_SMEM>>>(qkv, vT, attn);

    gemm_mma<<<dim3(E_ / 128, M_TOK / 128), 256, SMEM_GEMM>>>(
        attn, E_, wprojT, E_, y, E_, E_);
}

// round 8
// speedup vs baseline: 1.5690x; 1.5690x over previous
#include <cuda_runtime.h>
#include <cstdint>
#include <math.h>

using ll = long long;

constexpr int B_ = 4, S_ = 2048, E_ = 2048, H_ = 16, D_ = 128;
constexpr int M_TOK = B_ * S_;        // 8192
constexpr int QKV_N = 3 * H_ * D_;    // 6144
constexpr float RMS_EPS = 0.01f;
constexpr float SM_SCALE = 0.08838834764831845f;  // 1/sqrt(128)
constexpr float LOG2E = 1.4426950408889634f;

// ---------------- scratch (static device arrays; no cudaMalloc) ------------
__device__ float g_xr[(size_t)M_TOK * E_];             // 64 MB
__device__ float g_qkv[(size_t)M_TOK * QKV_N];         // 201 MB
__device__ float g_wqkvT[(size_t)QKV_N * E_];          // 50 MB
__device__ float g_wprojT[(size_t)E_ * E_];            // 16 MB
__device__ float g_vT[(size_t)B_ * H_ * D_ * S_];      // 67 MB
__device__ float g_attn[(size_t)M_TOK * H_ * D_];      // 67 MB
__device__ float g_cos[S_ * 64];
__device__ float g_sin[S_ * 64];

// ---------------- helpers --------------------------------------------------
__device__ __forceinline__ float rnd_tf32(float x) {
    uint32_t u;
    asm("cvt.rna.tf32.f32 %0, %1;" : "=r"(u) : "f"(x));
    return __uint_as_float(u);
}
__device__ __forceinline__ float ex2f(float x) {
    float y;
    asm("ex2.approx.ftz.f32 %0, %1;" : "=f"(y) : "f"(x));
    return y;
}
__device__ __forceinline__ uint32_t smem_u32(const void* p) {
    uint32_t a;
    asm("{ .reg .u64 t; cvta.to.shared.u64 t, %1; cvt.u32.u64 %0, t; }"
        : "=r"(a) : "l"(p));
    return a;
}
#define SWZ128(off) ((off) ^ (((off) >> 3) & 0x70))

// ---------------------------------------------------------------------------
__global__ void rope_table_kernel() {
    int idx = blockIdx.x * blockDim.x + threadIdx.x;
    if (idx >= S_ * 64) return;
    int s = idx >> 6, d = idx & 63;
    double f = pow(10000.0, -(double)d / 64.0);
    double ang = (double)s * f;
    g_cos[idx] = (float)cos(ang);
    g_sin[idx] = (float)sin(ang);
}

__global__ void round_copy(const float* __restrict__ in, float* __restrict__ out,
                           int n4) {
    int i = blockIdx.x * blockDim.x + threadIdx.x;
    if (i >= n4) return;
    float4 v = ((const float4*)in)[i];
    v.x = rnd_tf32(v.x); v.y = rnd_tf32(v.y);
    v.z = rnd_tf32(v.z); v.w = rnd_tf32(v.w);
    ((float4*)out)[i] = v;
}

__global__ void transpose_round(const float* __restrict__ in, ll ldi, ll sIb, ll sIh,
                                float* __restrict__ out, ll ldo, ll sOb, ll sOh) {
    __shared__ float t[32][33];
    const int z = blockIdx.z, zb = z >> 4, zh = z & 15;
    in += zb * sIb + zh * sIh;
    out += zb * sOb + zh * sOh;
    int k0 = blockIdx.y * 32, n0 = blockIdx.x * 32;
    int tx = threadIdx.x, ty = threadIdx.y;
#pragma unroll
    for (int i = 0; i < 4; i++)
        t[ty + i * 8][tx] = in[(ll)(k0 + ty + i * 8) * ldi + n0 + tx];
    __syncthreads();
#pragma unroll
    for (int i = 0; i < 4; i++)
        out[(ll)(n0 + ty + i * 8) * ldo + k0 + tx] = rnd_tf32(t[tx][ty + i * 8]);
}

__global__ void norm_rope_kernel(const float* __restrict__ qw,
                                 const float* __restrict__ kw) {
    int gw = blockIdx.x * 8 + (threadIdx.x >> 5);
    int lane = threadIdx.x & 31;
    int m = gw >> 5;
    int rem = gw & 31;
    int qk = rem >> 4;
    int h = rem & 15;
    float* p = g_qkv + (size_t)m * QKV_N + qk * (H_ * D_) + h * D_;

    float x0 = p[lane], x1 = p[lane + 32], x2 = p[lane + 64], x3 = p[lane + 96];
    float ss = x0 * x0 + x1 * x1 + x2 * x2 + x3 * x3;
#pragma unroll
    for (int o = 16; o; o >>= 1) ss += __shfl_xor_sync(0xffffffffu, ss, o);
    float inv = rsqrtf(ss * (1.0f / 128.0f) + RMS_EPS);

    const float* w = qk ? kw : qw;
    float n0 = x0 * inv * w[lane];
    float n1 = x1 * inv * w[lane + 32];
    float n2 = x2 * inv * w[lane + 64];
    float n3 = x3 * inv * w[lane + 96];

    int s = m & (S_ - 1);
    float c0 = g_cos[s * 64 + lane],      sn0 = g_sin[s * 64 + lane];
    float c1 = g_cos[s * 64 + lane + 32], sn1 = g_sin[s * 64 + lane + 32];

    float o0 = n0 * c0 - n2 * sn0;
    float o1 = n1 * c1 - n3 * sn1;
    float o2 = n2 * c0 + n0 * sn0;
    float o3 = n3 * c1 + n1 * sn1;
    if (!qk) { o0 *= SM_SCALE; o1 *= SM_SCALE; o2 *= SM_SCALE; o3 *= SM_SCALE; }
    p[lane]      = rnd_tf32(o0);
    p[lane + 32] = rnd_tf32(o1);
    p[lane + 64] = rnd_tf32(o2);
    p[lane + 96] = rnd_tf32(o3);
}

// ---------------------------------------------------------------------------
// tf32 mma.sync GEMM: C[M,N] = A[M,K] * B[N,K]^T (both K-major in gmem).
// 128x128 CTA tile, BK=32 (SW128), 3-stage cp.async pipeline -> 96KB smem
// -> 2 CTAs/SM. 256 threads, 8 warps of 64x32, x2 B-fragment loads (R5 form).
// ---------------------------------------------------------------------------
constexpr int N_STAGE = 3;
constexpr int STAGE_BYTES = 32768;
constexpr int SMEM_GEMM = N_STAGE * STAGE_BYTES;  // 96 KB

__global__ __launch_bounds__(256, 2) void gemm_mma(
    const float* __restrict__ A, ll lda,
    const float* __restrict__ B, ll ldb,
    float* __restrict__ C, ll ldc, int K) {
    const int bx = blockIdx.x, by = blockIdx.y;
    const int m0 = by * 128, n0 = bx * 128;
    const int nT = K >> 5;

    extern __shared__ char smem[];
    const uint32_t base = smem_u32(smem);

    const int tid = threadIdx.x;
    const int warp = tid >> 5, lane = tid & 31;
    const int wm = warp >> 2, wn = warp & 3;

    const int c16 = (tid & 7) * 16;
    const int r0 = tid >> 3;

    auto load_stage = [&](int kt) {
        const int buf = kt % 3;
        const uint32_t sa = base + buf * STAGE_BYTES;
        const uint32_t sb = sa + 16384;
        const float* Ap = A + kt * 32;
        const float* Bp = B + kt * 32;
#pragma unroll
        for (int p = 0; p < 4; p++) {
            int r = r0 + p * 32;
            uint32_t off = SWZ128((uint32_t)(r * 128 + c16));
            const char* ga = (const char*)(Ap + (ll)(m0 + r) * lda) + c16;
            asm volatile("cp.async.cg.shared.global [%0], [%1], 16;"
                         :: "r"(sa + off), "l"(ga));
            const char* gb = (const char*)(Bp + (ll)(n0 + r) * ldb) + c16;
            asm volatile("cp.async.cg.shared.global [%0], [%1], 16;"
                         :: "r"(sb + off), "l"(gb));
        }
        asm volatile("cp.async.commit_group;" ::: "memory");
    };

    const int lq = lane & 7;
    const int aRowIn16 = lq + (((lane >> 3) & 1) << 3);
    const int aSel = lane >> 4;
    const int bSel = (lane >> 3) & 1;

    float acc[4][4][4];
#pragma unroll
    for (int i = 0; i < 4; i++)
#pragma unroll
        for (int j = 0; j < 4; j++)
#pragma unroll
            for (int r = 0; r < 4; r++) acc[i][j][r] = 0.0f;

    load_stage(0);
    load_stage(1);

    for (int kt = 0; kt < nT; kt++) {
        asm volatile("cp.async.wait_group 1;" ::: "memory");
        __syncthreads();
        if (kt + 2 < nT) load_stage(kt + 2);
        else asm volatile("cp.async.commit_group;" ::: "memory");

        const int buf = kt % 3;
        const uint32_t sa = base + buf * STAGE_BYTES;
        const uint32_t sb = sa + 16384;
        const uint32_t aBase = sa + (uint32_t)(wm * 64 + aRowIn16) * 128;
        const uint32_t bBase = sb + (uint32_t)(wn * 32 + lq) * 128;

#pragma unroll
        for (int g = 0; g < 4; g++) {
            uint32_t af[4][4];
#pragma unroll
            for (int i = 0; i < 4; i++) {
                uint32_t addr = aBase + i * 16 * 128 +
                                16u * (uint32_t)(((g << 1) | aSel) ^ lq);
                asm volatile(
                    "ldmatrix.sync.aligned.m8n8.x4.shared.b16 {%0,%1,%2,%3}, [%4];"
                    : "=r"(af[i][0]), "=r"(af[i][1]), "=r"(af[i][2]), "=r"(af[i][3])
                    : "r"(addr));
            }
            uint32_t bf[4][2];
#pragma unroll
            for (int j = 0; j < 4; j++) {
                uint32_t addr = bBase + j * 8 * 128 +
                                16u * (uint32_t)(((g << 1) | bSel) ^ lq);
                asm volatile(
                    "ldmatrix.sync.aligned.m8n8.x2.shared.b16 {%0,%1}, [%2];"
                    : "=r"(bf[j][0]), "=r"(bf[j][1]) : "r"(addr));
            }
#pragma unroll
            for (int i = 0; i < 4; i++)
#pragma unroll
                for (int j = 0; j < 4; j++) {
                    asm volatile(
                        "mma.sync.aligned.m16n8k8.row.col.f32.tf32.tf32.f32 "
                        "{%0,%1,%2,%3}, {%4,%5,%6,%7}, {%8,%9}, {%0,%1,%2,%3};"
                        : "+f"(acc[i][j][0]), "+f"(acc[i][j][1]),
                          "+f"(acc[i][j][2]), "+f"(acc[i][j][3])
                        : "r"(af[i][0]), "r"(af[i][1]), "r"(af[i][2]), "r"(af[i][3]),
                          "r"(bf[j][0]), "r"(bf[j][1]));
                }
        }
    }

    float* Cw = C + (ll)(m0 + wm * 64) * ldc + n0 + wn * 32;
    const int erow = lane >> 2, ecol = (lane & 3) * 2;
#pragma unroll
    for (int i = 0; i < 4; i++)
#pragma unroll
        for (int j = 0; j < 4; j++) {
            float2 v0, v1;
            v0.x = acc[i][j][0]; v0.y = acc[i][j][1];
            v1.x = acc[i][j][2]; v1.y = acc[i][j][3];
            float* cp = Cw + (ll)(i * 16 + erow) * ldc + j * 8 + ecol;
            *(float2*)cp = v0;
            *(float2*)(cp + 8 * ldc) = v1;
        }
}

// ---------------------------------------------------------------------------
// Fused flash attention (causal), exact R5 form (x2 B-fragment loads).
// ---------------------------------------------------------------------------
constexpr int FA_SMEM = 65536 + 65536;

__global__ __launch_bounds__(256) void fa_kernel(
    const float* __restrict__ qkv_, const float* __restrict__ vT_,
    float* __restrict__ attn_) {
    const int qi = 15 - (int)blockIdx.x;       // heavy tiles first
    const int bh = blockIdx.y, b = bh >> 4, h = bh & 15;
    const float* Qb = qkv_ + (ll)(b * S_ + qi * 128) * QKV_N + h * 128;
    const float* Kb = qkv_ + (ll)b * S_ * QKV_N + H_ * D_ + h * 128;
    const float* Vb = vT_ + (ll)bh * D_ * S_;
    float* Ob = attn_ + (ll)(b * S_ + qi * 128) * (H_ * D_) + h * 128;

    extern __shared__ char smem[];
    const uint32_t qs = smem_u32(smem);
    const uint32_t ring = qs + 65536;

    const int tid = threadIdx.x, warp = tid >> 5, lane = tid & 31;
    const int c16 = (tid & 7) * 16, r0 = tid >> 3;

#pragma unroll
    for (int c = 0; c < 4; c++) {
#pragma unroll
        for (int p = 0; p < 4; p++) {
            int r = r0 + p * 32;
            uint32_t off = SWZ128((uint32_t)(r * 128 + c16));
            const char* g = (const char*)(Qb + (ll)r * QKV_N + c * 32) + c16;
            asm volatile("cp.async.cg.shared.global [%0], [%1], 16;"
                         :: "r"(qs + c * 16384 + off), "l"(g));
        }
    }
    asm volatile("cp.async.commit_group;" ::: "memory");

    const int total = (qi + 1) * 8;
    auto issue = [&](int ci) {
        if (ci < total) {
            const int kt = ci >> 3, rr = ci & 7;
            const float* gp;
            ll stride;
            if (rr < 4) { gp = Kb + (ll)kt * 128 * QKV_N + rr * 32; stride = QKV_N; }
            else        { gp = Vb + kt * 128 + (rr - 4) * 32;       stride = S_; }
            const uint32_t sa = ring + (ci & 3) * 16384;
#pragma unroll
            for (int p = 0; p < 4; p++) {
                int r = r0 + p * 32;
                uint32_t off = SWZ128((uint32_t)(r * 128 + c16));
                const char* g = (const char*)(gp + (ll)r * stride) + c16;
                asm volatile("cp.async.cg.shared.global [%0], [%1], 16;"
                             :: "r"(sa + off), "l"(g));
            }
        }
        asm volatile("cp.async.commit_group;" ::: "memory");
    };
    issue(0); issue(1); issue(2);

    const int lq = lane & 7;
    const int aRowIn16 = lq + (((lane >> 3) & 1) << 3);
    const int aSel = lane >> 4;
    const int bSel = (lane >> 3) & 1;
    const int q4 = lane & 3;

    float m0 = -1e30f, m1 = -1e30f, l0 = 0.0f, l1 = 0.0f;
    float accO[16][4];
#pragma unroll
    for (int j = 0; j < 16; j++)
#pragma unroll
        for (int r = 0; r < 4; r++) accO[j][r] = 0.0f;

    int ci = 0;
    for (int kt = 0; kt <= qi; kt++) {
        float accS[16][4];
#pragma unroll
        for (int j = 0; j < 16; j++)
#pragma unroll
            for (int r = 0; r < 4; r++) accS[j][r] = 0.0f;

        // ---- S = Q * K^T over 4 d-chunks --------------------------------
        for (int c = 0; c < 4; c++) {
            asm volatile("cp.async.wait_group 2;" ::: "memory");
            __syncthreads();
            issue(ci + 3);
            const uint32_t sk = ring + (ci & 3) * 16384;
            const uint32_t aB = qs + c * 16384 + (uint32_t)(warp * 16 + aRowIn16) * 128;
#pragma unroll
            for (int g = 0; g < 4; g++) {
                uint32_t af[4];
                uint32_t aaddr = aB + 16u * (uint32_t)(((g << 1) | aSel) ^ lq);
                asm volatile(
                    "ldmatrix.sync.aligned.m8n8.x4.shared.b16 {%0,%1,%2,%3}, [%4];"
                    : "=r"(af[0]), "=r"(af[1]), "=r"(af[2]), "=r"(af[3])
                    : "r"(aaddr));
#pragma unroll
                for (int j2 = 0; j2 < 16; j2++) {
                    uint32_t bf0, bf1;
                    uint32_t baddr = sk + (uint32_t)(j2 * 8 + lq) * 128 +
                                     16u * (uint32_t)(((g << 1) | bSel) ^ lq);
                    asm volatile(
                        "ldmatrix.sync.aligned.m8n8.x2.shared.b16 {%0,%1}, [%2];"
                        : "=r"(bf0), "=r"(bf1) : "r"(baddr));
                    asm volatile(
                        "mma.sync.aligned.m16n8k8.row.col.f32.tf32.tf32.f32 "
                        "{%0,%1,%2,%3}, {%4,%5,%6,%7}, {%8,%9}, {%0,%1,%2,%3};"
                        : "+f"(accS[j2][0]), "+f"(accS[j2][1]),
                          "+f"(accS[j2][2]), "+f"(accS[j2][3])
                        : "r"(af[0]), "r"(af[1]), "r"(af[2]), "r"(af[3]),
                          "r"(bf0), "r"(bf1));
                }
            }
            ci++;
        }

        // ---- causal mask on diagonal tile -------------------------------
        const int rW = warp * 16 + (lane >> 2);
        if (kt == qi) {
#pragma unroll
            for (int j2 = 0; j2 < 16; j2++) {
                int col = j2 * 8 + (q4 << 1);
                if (col     > rW)     accS[j2][0] = -1e30f;
                if (col + 1 > rW)     accS[j2][1] = -1e30f;
                if (col     > rW + 8) accS[j2][2] = -1e30f;
                if (col + 1 > rW + 8) accS[j2][3] = -1e30f;
            }
        }

        // ---- online softmax update --------------------------------------
        float mx0 = -1e30f, mx1 = -1e30f;
#pragma unroll
        for (int j2 = 0; j2 < 16; j2++) {
            mx0 = fmaxf(mx0, fmaxf(accS[j2][0], accS[j2][1]));
            mx1 = fmaxf(mx1, fmaxf(accS[j2][2], accS[j2][3]));
        }
        mx0 = fmaxf(mx0, __shfl_xor_sync(0xffffffffu, mx0, 1));
        mx0 = fmaxf(mx0, __shfl_xor_sync(0xffffffffu, mx0, 2));
        mx1 = fmaxf(mx1, __shfl_xor_sync(0xffffffffu, mx1, 1));
        mx1 = fmaxf(mx1, __shfl_xor_sync(0xffffffffu, mx1, 2));
        const float mn0 = fmaxf(m0, mx0), mn1 = fmaxf(m1, mx1);
        const float sc0 = ex2f((m0 - mn0) * LOG2E);
        const float sc1 = ex2f((m1 - mn1) * LOG2E);
        float rs0 = 0.0f, rs1 = 0.0f;
#pragma unroll
        for (int j2 = 0; j2 < 16; j2++) {
            float p0 = ex2f((accS[j2][0] - mn0) * LOG2E);
            float p1 = ex2f((accS[j2][1] - mn0) * LOG2E);
            float p2 = ex2f((accS[j2][2] - mn1) * LOG2E);
            float p3 = ex2f((accS[j2][3] - mn1) * LOG2E);
            rs0 += p0 + p1;
            rs1 += p2 + p3;
            accS[j2][0] = rnd_tf32(p0);
            accS[j2][1] = rnd_tf32(p1);
            accS[j2][2] = rnd_tf32(p2);
            accS[j2][3] = rnd_tf32(p3);
        }
        rs0 += __shfl_xor_sync(0xffffffffu, rs0, 1);
        rs0 += __shfl_xor_sync(0xffffffffu, rs0, 2);
        rs1 += __shfl_xor_sync(0xffffffffu, rs1, 1);
        rs1 += __shfl_xor_sync(0xffffffffu, rs1, 2);
        l0 = l0 * sc0 + rs0;
        l1 = l1 * sc1 + rs1;
#pragma unroll
        for (int j2 = 0; j2 < 16; j2++) {
            accO[j2][0] *= sc0; accO[j2][1] *= sc0;
            accO[j2][2] *= sc1; accO[j2][3] *= sc1;
        }
        m0 = mn0; m1 = mn1;

        // ---- accO += P * V over 4 s-chunks ------------------------------
        const int sbase = lane & ~3;
        const int s1 = sbase + (q4 >> 1), s2 = s1 + 2;
        const bool odd = (q4 & 1);
        for (int cc = 0; cc < 4; cc++) {
            asm volatile("cp.async.wait_group 2;" ::: "memory");
            __syncthreads();
            issue(ci + 3);
            const uint32_t sv = ring + (ci & 3) * 16384;
#pragma unroll
            for (int g = 0; g < 4; g++) {
                const int jt = cc * 4 + g;
                float v00 = __shfl_sync(0xffffffffu, accS[jt][0], s1);
                float v01 = __shfl_sync(0xffffffffu, accS[jt][1], s1);
                float v02 = __shfl_sync(0xffffffffu, accS[jt][0], s2);
                float v03 = __shfl_sync(0xffffffffu, accS[jt][1], s2);
                float v10 = __shfl_sync(0xffffffffu, accS[jt][2], s1);
                float v11 = __shfl_sync(0xffffffffu, accS[jt][3], s1);
                float v12 = __shfl_sync(0xffffffffu, accS[jt][2], s2);
                float v13 = __shfl_sync(0xffffffffu, accS[jt][3], s2);
                uint32_t a0 = __float_as_uint(odd ? v01 : v00);
                uint32_t a2 = __float_as_uint(odd ? v03 : v02);
                uint32_t a1 = __float_as_uint(odd ? v11 : v10);
                uint32_t a3 = __float_as_uint(odd ? v13 : v12);
#pragma unroll
                for (int j2 = 0; j2 < 16; j2++) {
                    uint32_t bf0, bf1;
                    uint32_t baddr = sv + (uint32_t)(j2 * 8 + lq) * 128 +
                                     16u * (uint32_t)(((g << 1) | bSel) ^ lq);
                    asm volatile(
                        "ldmatrix.sync.aligned.m8n8.x2.shared.b16 {%0,%1}, [%2];"
                        : "=r"(bf0), "=r"(bf1) : "r"(baddr));
                    asm volatile(
                        "mma.sync.aligned.m16n8k8.row.col.f32.tf32.tf32.f32 "
                        "{%0,%1,%2,%3}, {%4,%5,%6,%7}, {%8,%9}, {%0,%1,%2,%3};"
                        : "+f"(accO[j2][0]), "+f"(accO[j2][1]),
                          "+f"(accO[j2][2]), "+f"(accO[j2][3])
                        : "r"(a0), "r"(a1), "r"(a2), "r"(a3),
                          "r"(bf0), "r"(bf1));
                }
            }
            ci++;
        }
    }

    // ---- normalize + store -----------------------------------------------
    const float inv0 = 1.0f / l0, inv1 = 1.0f / l1;
    const int rW = warp * 16 + (lane >> 2);
    float* o0 = Ob + (ll)rW * (H_ * D_) + (q4 << 1);
    float* o1 = o0 + 8 * (H_ * D_);
#pragma unroll
    for (int j2 = 0; j2 < 16; j2++) {
        float2 v0, v1;
        v0.x = rnd_tf32(accO[j2][0] * inv0);
        v0.y = rnd_tf32(accO[j2][1] * inv0);
        v1.x = rnd_tf32(accO[j2][2] * inv1);
        v1.y = rnd_tf32(accO[j2][3] * inv1);
        *(float2*)(o0 + j2 * 8) = v0;
        *(float2*)(o1 + j2 * 8) = v1;
    }
}

// ---------------------------------------------------------------------------
extern "C" void kernel_launch(void* const* d_in, const int* in_sizes, int n_in,
                              void* d_out, int out_size) {
    const float* x  = (const float*)d_in[0];
    const float* wq = (const float*)d_in[1];
    const float* wp = (const float*)d_in[2];
    const float* qw = (const float*)d_in[3];
    const float* kw = (const float*)d_in[4];
    float* y = (float*)d_out;

    float *xr, *qkv, *wqkvT, *wprojT, *vT, *attn;
    cudaGetSymbolAddress((void**)&xr, g_xr);
    cudaGetSymbolAddress((void**)&qkv, g_qkv);
    cudaGetSymbolAddress((void**)&wqkvT, g_wqkvT);
    cudaGetSymbolAddress((void**)&wprojT, g_wprojT);
    cudaGetSymbolAddress((void**)&vT, g_vT);
    cudaGetSymbolAddress((void**)&attn, g_attn);

    cudaFuncSetAttribute(gemm_mma,
                         cudaFuncAttributeMaxDynamicSharedMemorySize, SMEM_GEMM);
    cudaFuncSetAttribute(fa_kernel,
                         cudaFuncAttributeMaxDynamicSharedMemorySize, FA_SMEM);

    // launch index:                                     (ncu captures idx 3)
    // 0 rope, 1 round, 2 wqkvT, 3 QKV GEMM, 4 norm_rope, 5 wprojT, 6 vT,
    // 7 fa, 8 proj GEMM
    rope_table_kernel<<<(S_ * 64 + 255) / 256, 256>>>();
    round_copy<<<(M_TOK * E_ / 4 + 255) / 256, 256>>>(x, xr, M_TOK * E_ / 4);
    transpose_round<<<dim3(QKV_N / 32, E_ / 32, 1), dim3(32, 8)>>>(
        wq, QKV_N, 0, 0, wqkvT, E_, 0, 0);

    gemm_mma<<<dim3(QKV_N / 128, M_TOK / 128), 256, SMEM_GEMM>>>(
        xr, E_, wqkvT, E_, qkv, QKV_N, E_);

    norm_rope_kernel<<<(2 * M_TOK * H_) / 8, 256>>>(qw, kw);

    transpose_round<<<dim3(E_ / 32, E_ / 32, 1), dim3(32, 8)>>>(
        wp, E_, 0, 0, wprojT, E_, 0, 0);

    transpose_round<<<dim3(D_ / 32, S_ / 32, B_ * H_), dim3(32, 8)>>>(
        qkv + 2 * H_ * D_, QKV_N, (ll)S_ * QKV_N, 128,
        vT, S_, (ll)H_ * D_ * S_, (ll)D_ * S_);

    fa_kernel<<<dim3(16, 64), 256, FA_SMEM>>>(qkv, vT, attn);

    gemm_mma<<<dim3(E_ / 128, M_TOK / 128), 256, SMEM_GEMM>>>(
        attn, E_, wprojT, E_, y, E_, E_);
}

// round 10
// speedup vs baseline: 2.8793x; 1.8351x over previous
#include <cuda_runtime.h>
#include <cuda_fp16.h>
#include <cstdint>
#include <math.h>

using ll = long long;

constexpr int B_ = 4, S_ = 2048, E_ = 2048, H_ = 16, D_ = 128;
constexpr int M_TOK = B_ * S_;        // 8192
constexpr int QKV_N = 3 * H_ * D_;    // 6144
constexpr int HD = H_ * D_;           // 2048
constexpr float RMS_EPS = 0.01f;
constexpr float SM_SCALE = 0.08838834764831845f;  // 1/sqrt(128)
constexpr float LOG2E = 1.4426950408889634f;

// ---------------- scratch (static device arrays; no cudaMalloc) ------------
__device__ __half g_xh[(size_t)M_TOK * E_];            // 32 MB
__device__ float  g_qkv[(size_t)M_TOK * QKV_N];        // 201 MB
__device__ __half g_wqkvT[(size_t)QKV_N * E_];         // 25 MB
__device__ __half g_wprojT[(size_t)E_ * E_];           // 8 MB
__device__ __half g_qh[(size_t)M_TOK * HD];            // 32 MB
__device__ __half g_kh[(size_t)M_TOK * HD];            // 32 MB
__device__ __half g_vT[(size_t)B_ * H_ * D_ * S_];     // 32 MB
__device__ __half g_attnh[(size_t)M_TOK * HD];         // 32 MB
__device__ float g_cos[S_ * 64];
__device__ float g_sin[S_ * 64];

// ---------------- helpers --------------------------------------------------
__device__ __forceinline__ uint32_t pack_h2(float lo, float hi) {
    uint32_t u;
    asm("cvt.rn.f16x2.f32 %0, %1, %2;" : "=r"(u) : "f"(hi), "f"(lo));
    return u;
}
__device__ __forceinline__ float ex2f(float x) {
    float y;
    asm("ex2.approx.ftz.f32 %0, %1;" : "=f"(y) : "f"(x));
    return y;
}
__device__ __forceinline__ uint32_t smem_u32(const void* p) {
    uint32_t a;
    asm("{ .reg .u64 t; cvta.to.shared.u64 t, %1; cvt.u32.u64 %0, t; }"
        : "=r"(a) : "l"(p));
    return a;
}
#define SWZ128(off) ((off) ^ (((off) >> 3) & 0x70))

#define MMA_F16(d, a, b)                                                     \
    asm volatile(                                                            \
        "mma.sync.aligned.m16n8k16.row.col.f32.f16.f16.f32 "                 \
        "{%0,%1,%2,%3}, {%4,%5,%6,%7}, {%8,%9}, {%0,%1,%2,%3};"              \
        : "+f"((d)[0]), "+f"((d)[1]), "+f"((d)[2]), "+f"((d)[3])             \
        : "r"((a)[0]), "r"((a)[1]), "r"((a)[2]), "r"((a)[3]),                \
          "r"((b)[0]), "r"((b)[1]))

// ---------------------------------------------------------------------------
__global__ void rope_table_kernel() {
    int idx = blockIdx.x * blockDim.x + threadIdx.x;
    if (idx >= S_ * 64) return;
    int s = idx >> 6, d = idx & 63;
    double f = pow(10000.0, -(double)d / 64.0);
    double ang = (double)s * f;
    g_cos[idx] = (float)cos(ang);
    g_sin[idx] = (float)sin(ang);
}

__global__ void half_copy(const float* __restrict__ in, __half* __restrict__ out,
                          int n4) {
    int i = blockIdx.x * blockDim.x + threadIdx.x;
    if (i >= n4) return;
    float4 v = ((const float4*)in)[i];
    uint2 o;
    o.x = pack_h2(v.x, v.y);
    o.y = pack_h2(v.z, v.w);
    ((uint2*)out)[i] = o;
}

// Batched transpose fp32 -> half: out[n][k] = half(in[k][n])
__global__ void transpose_half(const float* __restrict__ in, ll ldi, ll sIb, ll sIh,
                               __half* __restrict__ out, ll ldo, ll sOb, ll sOh) {
    __shared__ float t[32][33];
    const int z = blockIdx.z, zb = z >> 4, zh = z & 15;
    in += zb * sIb + zh * sIh;
    out += zb * sOb + zh * sOh;
    int k0 = blockIdx.y * 32, n0 = blockIdx.x * 32;
    int tx = threadIdx.x, ty = threadIdx.y;
#pragma unroll
    for (int i = 0; i < 4; i++)
        t[ty + i * 8][tx] = in[(ll)(k0 + ty + i * 8) * ldi + n0 + tx];
    __syncthreads();
#pragma unroll
    for (int i = 0; i < 4; i++)
        out[(ll)(n0 + ty + i * 8) * ldo + k0 + tx] =
            __float2half_rn(t[tx][ty + i * 8]);
}

// RMSNorm + RoPE (+ fold softmax scale into q); fp32 in, half out
__global__ void norm_rope_kernel(const float* __restrict__ qw,
                                 const float* __restrict__ kw) {
    int gw = blockIdx.x * 8 + (threadIdx.x >> 5);
    int lane = threadIdx.x & 31;
    int m = gw >> 5;
    int rem = gw & 31;
    int qk = rem >> 4;
    int h = rem & 15;
    const float* p = g_qkv + (size_t)m * QKV_N + qk * HD + h * D_;
    __half* o = (qk ? g_kh : g_qh) + (size_t)m * HD + h * D_;

    float x0 = p[lane], x1 = p[lane + 32], x2 = p[lane + 64], x3 = p[lane + 96];
    float ss = x0 * x0 + x1 * x1 + x2 * x2 + x3 * x3;
#pragma unroll
    for (int of = 16; of; of >>= 1) ss += __shfl_xor_sync(0xffffffffu, ss, of);
    float inv = rsqrtf(ss * (1.0f / 128.0f) + RMS_EPS);

    const float* w = qk ? kw : qw;
    float n0 = x0 * inv * w[lane];
    float n1 = x1 * inv * w[lane + 32];
    float n2 = x2 * inv * w[lane + 64];
    float n3 = x3 * inv * w[lane + 96];

    int s = m & (S_ - 1);
    float c0 = g_cos[s * 64 + lane],      sn0 = g_sin[s * 64 + lane];
    float c1 = g_cos[s * 64 + lane + 32], sn1 = g_sin[s * 64 + lane + 32];

    float o0 = n0 * c0 - n2 * sn0;
    float o1 = n1 * c1 - n3 * sn1;
    float o2 = n2 * c0 + n0 * sn0;
    float o3 = n3 * c1 + n1 * sn1;
    if (!qk) { o0 *= SM_SCALE; o1 *= SM_SCALE; o2 *= SM_SCALE; o3 *= SM_SCALE; }
    o[lane]      = __float2half_rn(o0);
    o[lane + 32] = __float2half_rn(o1);
    o[lane + 64] = __float2half_rn(o2);
    o[lane + 96] = __float2half_rn(o3);
}

// ---------------------------------------------------------------------------
// fp16 mma.sync GEMM: C[M,N] = A[M,K] * B[N,K]^T (half, K-major; C fp32).
// 128x128 CTA tile, BK=64 halves (128B rows, SW128), 3-stage cp.async,
// 2 CTAs/SM. 8 warps of 64x32.
// ---------------------------------------------------------------------------
constexpr int STAGE_BYTES = 32768;                // A 16KB + B 16KB
constexpr int SMEM_GEMM = 3 * STAGE_BYTES;        // 96 KB

__global__ __launch_bounds__(256, 2) void gemm_h(
    const __half* __restrict__ A, ll lda,
    const __half* __restrict__ B, ll ldb,
    float* __restrict__ C, ll ldc, int K) {
    const int bx = blockIdx.x, by = blockIdx.y;
    const int m0 = by * 128, n0 = bx * 128;
    const int nT = K >> 6;

    extern __shared__ char smem[];
    const uint32_t base = smem_u32(smem);

    const int tid = threadIdx.x;
    const int warp = tid >> 5, lane = tid & 31;
    const int wm = warp >> 2, wn = warp & 3;

    const int c16 = (tid & 7) * 16;
    const int r0 = tid >> 3;

    auto load_stage = [&](int kt) {
        const int buf = kt % 3;
        const uint32_t sa = base + buf * STAGE_BYTES;
        const uint32_t sb = sa + 16384;
        const __half* Ap = A + kt * 64;
        const __half* Bp = B + kt * 64;
#pragma unroll
        for (int p = 0; p < 4; p++) {
            int r = r0 + p * 32;
            uint32_t off = SWZ128((uint32_t)(r * 128 + c16));
            const char* ga = (const char*)(Ap + (ll)(m0 + r) * lda) + c16;
            asm volatile("cp.async.cg.shared.global [%0], [%1], 16;"
                         :: "r"(sa + off), "l"(ga));
            const char* gb = (const char*)(Bp + (ll)(n0 + r) * ldb) + c16;
            asm volatile("cp.async.cg.shared.global [%0], [%1], 16;"
                         :: "r"(sb + off), "l"(gb));
        }
        asm volatile("cp.async.commit_group;" ::: "memory");
    };

    const int lq = lane & 7;
    const int aRowIn16 = lq + (((lane >> 3) & 1) << 3);
    const int aSel = lane >> 4;
    const int bSel = (lane >> 3) & 1;

    float acc[4][4][4];
#pragma unroll
    for (int i = 0; i < 4; i++)
#pragma unroll
        for (int j = 0; j < 4; j++)
#pragma unroll
            for (int r = 0; r < 4; r++) acc[i][j][r] = 0.0f;

    load_stage(0);
    load_stage(1);

    for (int kt = 0; kt < nT; kt++) {
        asm volatile("cp.async.wait_group 1;" ::: "memory");
        __syncthreads();
        if (kt + 2 < nT) load_stage(kt + 2);
        else asm volatile("cp.async.commit_group;" ::: "memory");

        const int buf = kt % 3;
        const uint32_t sa = base + buf * STAGE_BYTES;
        const uint32_t sb = sa + 16384;
        const uint32_t aBase = sa + (uint32_t)(wm * 64 + aRowIn16) * 128;
        const uint32_t bBase = sb + (uint32_t)(wn * 32 + lq) * 128;

#pragma unroll
        for (int g = 0; g < 4; g++) {
            uint32_t af[4][4];
#pragma unroll
            for (int i = 0; i < 4; i++) {
                uint32_t addr = aBase + i * 16 * 128 +
                                16u * (uint32_t)(((g << 1) | aSel) ^ lq);
                asm volatile(
                    "ldmatrix.sync.aligned.m8n8.x4.shared.b16 {%0,%1,%2,%3}, [%4];"
                    : "=r"(af[i][0]), "=r"(af[i][1]), "=r"(af[i][2]), "=r"(af[i][3])
                    : "r"(addr));
            }
            uint32_t bf[4][2];
#pragma unroll
            for (int j = 0; j < 4; j++) {
                uint32_t addr = bBase + j * 8 * 128 +
                                16u * (uint32_t)(((g << 1) | bSel) ^ lq);
                asm volatile(
                    "ldmatrix.sync.aligned.m8n8.x2.shared.b16 {%0,%1}, [%2];"
                    : "=r"(bf[j][0]), "=r"(bf[j][1]) : "r"(addr));
            }
#pragma unroll
            for (int i = 0; i < 4; i++)
#pragma unroll
                for (int j = 0; j < 4; j++) MMA_F16(acc[i][j], af[i], bf[j]);
        }
    }

    float* Cw = C + (ll)(m0 + wm * 64) * ldc + n0 + wn * 32;
    const int erow = lane >> 2, ecol = (lane & 3) * 2;
#pragma unroll
    for (int i = 0; i < 4; i++)
#pragma unroll
        for (int j = 0; j < 4; j++) {
            float2 v0, v1;
            v0.x = acc[i][j][0]; v0.y = acc[i][j][1];
            v1.x = acc[i][j][2]; v1.y = acc[i][j][3];
            float* cp = Cw + (ll)(i * 16 + erow) * ldc + j * 8 + ecol;
            *(float2*)cp = v0;
            *(float2*)(cp + 8 * ldc) = v1;
        }
}

// ---------------------------------------------------------------------------
// Fused flash attention (causal), fp16 operands. Per CTA one (q-tile, b, h).
// 8 warps x 16 q-rows. Q resident (2 x 16KB d-chunks); per k-block 4 ring
// chunks: K d-chunk0/1, V s-chunk0/1 (each 128 rows x 128B). P stays in
// registers; fp16 C->A fragment conversion is lane-local (no shfl).
// ---------------------------------------------------------------------------
constexpr int FA_SMEM = 32768 + 65536;  // Q + 4-stage ring

__global__ __launch_bounds__(256) void fa_kernel(
    const __half* __restrict__ qh_, const __half* __restrict__ kh_,
    const __half* __restrict__ vT_, __half* __restrict__ attn_) {
    const int qi = 15 - (int)blockIdx.x;       // heavy tiles first
    const int bh = blockIdx.y, b = bh >> 4, h = bh & 15;
    const __half* Qb = qh_ + (ll)(b * S_ + qi * 128) * HD + h * D_;
    const __half* Kb = kh_ + (ll)b * S_ * HD + h * D_;
    const __half* Vb = vT_ + (ll)bh * D_ * S_;
    __half* Ob = attn_ + (ll)(b * S_ + qi * 128) * HD + h * D_;

    extern __shared__ char smem[];
    const uint32_t qs = smem_u32(smem);
    const uint32_t ring = qs + 32768;

    const int tid = threadIdx.x, warp = tid >> 5, lane = tid & 31;
    const int c16 = (tid & 7) * 16, r0 = tid >> 3;

    // Q tile: 2 d-chunks of 128 rows x 128B
#pragma unroll
    for (int c = 0; c < 2; c++) {
#pragma unroll
        for (int p = 0; p < 4; p++) {
            int r = r0 + p * 32;
            uint32_t off = SWZ128((uint32_t)(r * 128 + c16));
            const char* g = (const char*)(Qb + (ll)r * HD) + c * 128 + c16;
            asm volatile("cp.async.cg.shared.global [%0], [%1], 16;"
                         :: "r"(qs + c * 16384 + off), "l"(g));
        }
    }
    asm volatile("cp.async.commit_group;" ::: "memory");

    const int total = (qi + 1) * 4;
    auto issue = [&](int ci) {
        if (ci < total) {
            const int kt = ci >> 2, rr = ci & 3;
            const uint32_t sa = ring + (ci & 3) * 16384;
            if (rr < 2) {  // K d-chunk rr
#pragma unroll
                for (int p = 0; p < 4; p++) {
                    int r = r0 + p * 32;
                    uint32_t off = SWZ128((uint32_t)(r * 128 + c16));
                    const char* g =
                        (const char*)(Kb + (ll)(kt * 128 + r) * HD) + rr * 128 + c16;
                    asm volatile("cp.async.cg.shared.global [%0], [%1], 16;"
                                 :: "r"(sa + off), "l"(g));
                }
            } else {       // V s-chunk rr-2 (rows = d)
#pragma unroll
                for (int p = 0; p < 4; p++) {
                    int r = r0 + p * 32;
                    uint32_t off = SWZ128((uint32_t)(r * 128 + c16));
                    const char* g = (const char*)(Vb + (ll)r * S_) + kt * 256 +
                                    (rr - 2) * 128 + c16;
                    asm volatile("cp.async.cg.shared.global [%0], [%1], 16;"
                                 :: "r"(sa + off), "l"(g));
                }
            }
        }
        asm volatile("cp.async.commit_group;" ::: "memory");
    };
    issue(0); issue(1); issue(2);

    const int lq = lane & 7;
    const int aRowIn16 = lq + (((lane >> 3) & 1) << 3);
    const int aSel = lane >> 4;
    const int bSel = (lane >> 3) & 1;
    const int q4 = lane & 3;

    float m0 = -1e30f, m1 = -1e30f, l0 = 0.0f, l1 = 0.0f;
    float accO[16][4];
#pragma unroll
    for (int j = 0; j < 16; j++)
#pragma unroll
        for (int r = 0; r < 4; r++) accO[j][r] = 0.0f;

    int ci = 0;
    for (int kt = 0; kt <= qi; kt++) {
        float accS[16][4];
#pragma unroll
        for (int j = 0; j < 16; j++)
#pragma unroll
            for (int r = 0; r < 4; r++) accS[j][r] = 0.0f;

        // ---- S = Q * K^T over 2 d-chunks (k16 x 4 per chunk) ------------
#pragma unroll
        for (int c = 0; c < 2; c++) {
            asm volatile("cp.async.wait_group 2;" ::: "memory");
            __syncthreads();
            issue(ci + 3);
            const uint32_t sk = ring + (ci & 3) * 16384;
            const uint32_t aB = qs + c * 16384 + (uint32_t)(warp * 16 + aRowIn16) * 128;
#pragma unroll
            for (int g = 0; g < 4; g++) {
                uint32_t af[4];
                uint32_t aaddr = aB + 16u * (uint32_t)(((g << 1) | aSel) ^ lq);
                asm volatile(
                    "ldmatrix.sync.aligned.m8n8.x4.shared.b16 {%0,%1,%2,%3}, [%4];"
                    : "=r"(af[0]), "=r"(af[1]), "=r"(af[2]), "=r"(af[3])
                    : "r"(aaddr));
#pragma unroll
                for (int j2 = 0; j2 < 16; j2++) {
                    uint32_t bf[2];
                    uint32_t baddr = sk + (uint32_t)(j2 * 8 + lq) * 128 +
                                     16u * (uint32_t)(((g << 1) | bSel) ^ lq);
                    asm volatile(
                        "ldmatrix.sync.aligned.m8n8.x2.shared.b16 {%0,%1}, [%2];"
                        : "=r"(bf[0]), "=r"(bf[1]) : "r"(baddr));
                    MMA_F16(accS[j2], af, bf);
                }
            }
            ci++;
        }

        // ---- causal mask on diagonal tile -------------------------------
        const int rW = warp * 16 + (lane >> 2);
        if (kt == qi) {
#pragma unroll
            for (int j2 = 0; j2 < 16; j2++) {
                int col = j2 * 8 + (q4 << 1);
                if (col     > rW)     accS[j2][0] = -1e30f;
                if (col + 1 > rW)     accS[j2][1] = -1e30f;
                if (col     > rW + 8) accS[j2][2] = -1e30f;
                if (col + 1 > rW + 8) accS[j2][3] = -1e30f;
            }
        }

        // ---- online softmax; P -> fp16 A-fragments (lane-local) ---------
        float mx0 = -1e30f, mx1 = -1e30f;
#pragma unroll
        for (int j2 = 0; j2 < 16; j2++) {
            mx0 = fmaxf(mx0, fmaxf(accS[j2][0], accS[j2][1]));
            mx1 = fmaxf(mx1, fmaxf(accS[j2][2], accS[j2][3]));
        }
        mx0 = fmaxf(mx0, __shfl_xor_sync(0xffffffffu, mx0, 1));
        mx0 = fmaxf(mx0, __shfl_xor_sync(0xffffffffu, mx0, 2));
        mx1 = fmaxf(mx1, __shfl_xor_sync(0xffffffffu, mx1, 1));
        mx1 = fmaxf(mx1, __shfl_xor_sync(0xffffffffu, mx1, 2));
        const float mn0 = fmaxf(m0, mx0), mn1 = fmaxf(m1, mx1);
        const float sc0 = ex2f((m0 - mn0) * LOG2E);
        const float sc1 = ex2f((m1 - mn1) * LOG2E);
        float rs0 = 0.0f, rs1 = 0.0f;
        uint32_t ph0[16], ph1[16];
#pragma unroll
        for (int j2 = 0; j2 < 16; j2++) {
            float p0 = ex2f((accS[j2][0] - mn0) * LOG2E);
            float p1 = ex2f((accS[j2][1] - mn0) * LOG2E);
            float p2 = ex2f((accS[j2][2] - mn1) * LOG2E);
            float p3 = ex2f((accS[j2][3] - mn1) * LOG2E);
            rs0 += p0 + p1;
            rs1 += p2 + p3;
            ph0[j2] = pack_h2(p0, p1);   // rows m      (a0/a2 source)
            ph1[j2] = pack_h2(p2, p3);   // rows m+8    (a1/a3 source)
        }
        rs0 += __shfl_xor_sync(0xffffffffu, rs0, 1);
        rs0 += __shfl_xor_sync(0xffffffffu, rs0, 2);
        rs1 += __shfl_xor_sync(0xffffffffu, rs1, 1);
        rs1 += __shfl_xor_sync(0xffffffffu, rs1, 2);
        l0 = l0 * sc0 + rs0;
        l1 = l1 * sc1 + rs1;
#pragma unroll
        for (int j2 = 0; j2 < 16; j2++) {
            accO[j2][0] *= sc0; accO[j2][1] *= sc0;
            accO[j2][2] *= sc1; accO[j2][3] *= sc1;
        }
        m0 = mn0; m1 = mn1;

        // ---- accO += P * V over 2 s-chunks (k16 x 4 per chunk) ----------
#pragma unroll
        for (int sc = 0; sc < 2; sc++) {
            asm volatile("cp.async.wait_group 2;" ::: "memory");
            __syncthreads();
            issue(ci + 3);
            const uint32_t sv = ring + (ci & 3) * 16384;
#pragma unroll
            for (int g = 0; g < 4; g++) {
                const int gk = sc * 4 + g;       // k16-step within s-block
                uint32_t af[4];
                af[0] = ph0[2 * gk];
                af[1] = ph1[2 * gk];
                af[2] = ph0[2 * gk + 1];
                af[3] = ph1[2 * gk + 1];
#pragma unroll
                for (int j2 = 0; j2 < 16; j2++) {
                    uint32_t bf[2];
                    uint32_t baddr = sv + (uint32_t)(j2 * 8 + lq) * 128 +
                                     16u * (uint32_t)(((g << 1) | bSel) ^ lq);
                    asm volatile(
                        "ldmatrix.sync.aligned.m8n8.x2.shared.b16 {%0,%1}, [%2];"
                        : "=r"(bf[0]), "=r"(bf[1]) : "r"(baddr));
                    MMA_F16(accO[j2], af, bf);
                }
            }
            ci++;
        }
    }

    // ---- normalize + store (half) ----------------------------------------
    const float inv0 = 1.0f / l0, inv1 = 1.0f / l1;
    const int rW = warp * 16 + (lane >> 2);
    __half* o0 = Ob + (ll)rW * HD + (q4 << 1);
    __half* o1 = o0 + 8 * HD;
#pragma unroll
    for (int j2 = 0; j2 < 16; j2++) {
        *(uint32_t*)(o0 + j2 * 8) = pack_h2(accO[j2][0] * inv0, accO[j2][1] * inv0);
        *(uint32_t*)(o1 + j2 * 8) = pack_h2(accO[j2][2] * inv1, accO[j2][3] * inv1);
    }
}

// ---------------------------------------------------------------------------
extern "C" void kernel_launch(void* const* d_in, const int* in_sizes, int n_in,
                              void* d_out, int out_size) {
    const float* x  = (const float*)d_in[0];
    const float* wq = (const float*)d_in[1];
    const float* wp = (const float*)d_in[2];
    const float* qw = (const float*)d_in[3];
    const float* kw = (const float*)d_in[4];
    float* y = (float*)d_out;

    __half *xh, *wqkvT, *wprojT, *qh, *kh, *vT, *attnh;
    float* qkv;
    cudaGetSymbolAddress((void**)&xh, g_xh);
    cudaGetSymbolAddress((void**)&qkv, g_qkv);
    cudaGetSymbolAddress((void**)&wqkvT, g_wqkvT);
    cudaGetSymbolAddress((void**)&wprojT, g_wprojT);
    cudaGetSymbolAddress((void**)&qh, g_qh);
    cudaGetSymbolAddress((void**)&kh, g_kh);
    cudaGetSymbolAddress((void**)&vT, g_vT);
    cudaGetSymbolAddress((void**)&attnh, g_attnh);

    cudaFuncSetAttribute(gemm_h,
                         cudaFuncAttributeMaxDynamicSharedMemorySize, SMEM_GEMM);
    cudaFuncSetAttribute(fa_kernel,
                         cudaFuncAttributeMaxDynamicSharedMemorySize, FA_SMEM);

    // launch index (ncu captures idx 3 = QKV GEMM):
    rope_table_kernel<<<(S_ * 64 + 255) / 256, 256>>>();
    half_copy<<<(M_TOK * E_ / 4 + 255) / 256, 256>>>(x, xh, M_TOK * E_ / 4);
    transpose_half<<<dim3(QKV_N / 32, E_ / 32, 1), dim3(32, 8)>>>(
        wq, QKV_N, 0, 0, wqkvT, E_, 0, 0);

    gemm_h<<<dim3(QKV_N / 128, M_TOK / 128), 256, SMEM_GEMM>>>(
        xh, E_, wqkvT, E_, qkv, QKV_N, E_);

    norm_rope_kernel<<<(2 * M_TOK * H_) / 8, 256>>>(qw, kw);

    transpose_half<<<dim3(E_ / 32, E_ / 32, 1), dim3(32, 8)>>>(
        wp, E_, 0, 0, wprojT, E_, 0, 0);

    // V: qkv fp32 [s][2HD + h*128 + d] -> vT half [bh][d][s]
    transpose_half<<<dim3(D_ / 32, S_ / 32, B_ * H_), dim3(32, 8)>>>(
        qkv + 2 * HD, QKV_N, (ll)S_ * QKV_N, 128,
        vT, S_, (ll)H_ * D_ * S_, (ll)D_ * S_);

    fa_kernel<<<dim3(16, 64), 256, FA_SMEM>>>(qh, kh, vT, attnh);

    gemm_h<<<dim3(E_ / 128, M_TOK / 128), 256, SMEM_GEMM>>>(
        attnh, HD, wprojT, E_, y, E_, E_);
}